// round 7
// baseline (speedup 1.0000x reference)
#include <cuda_runtime.h>

#define NTOT      40
#define NX        20
#define BATCHN    524288
#define TPB       256
#define WARPS     (TPB / 32)
#define ROWS_WI   16                     // rows per warp-iteration (2 lanes/row)
#define RITER     4                      // warp-iterations per warp
#define NBLOCKS   (BATCHN / (WARPS * RITER * ROWS_WI))   // 1024

// Per-block double partials (each block writes its own slot every launch).
__device__ double g_part_dd[NBLOCKS];
__device__ double g_part_pi[NBLOCKS];
__device__ unsigned int g_ticket = 0;    // re-armed to 0 by the last block

__global__ __launch_bounds__(TPB) void hybrid_loss_kernel(
    const float* __restrict__ pred,
    const float* __restrict__ targ,
    const float* __restrict__ ycur,
    float* __restrict__ out)
{
    const int t    = threadIdx.x;
    const int lane = t & 31;
    const int wid  = t >> 5;
    const int h    = lane & 1;           // 0: elements 0..19, 1: elements 20..39
    const int rw   = lane >> 1;          // row within warp-iteration (0..15)
    const int gw   = blockIdx.x * WARPS + wid;

    const float4* __restrict__ p4 = (const float4*)pred;
    const float4* __restrict__ y4 = (const float4*)ycur;
    const float4* __restrict__ t4 = (const float4*)targ;

    float acc_dd = 0.0f;
    float acc_pi = 0.0f;

    #pragma unroll
    for (int i = 0; i < RITER; ++i) {
        const int row = (gw * RITER + i) * ROWS_WI + rw;
        const int b   = row * 10 + h * 5;     // this lane's first float4 of the row

        // Own half-row: 5 independent LDG.128 each for pred and ycur.
        float4 X0 = p4[b+0], X1 = p4[b+1], X2 = p4[b+2], X3 = p4[b+3], X4 = p4[b+4];
        float4 Y0 = y4[b+0], Y1 = y4[b+1], Y2 = y4[b+2], Y3 = y4[b+3], Y4 = y4[b+4];

        // Targets: observed cols 0..19 == exactly the h==0 lane's slice.
        float4 T0, T1, T2, T3, T4;
        if (h == 0) {
            const int tb = row * 10;
            T0 = t4[tb+0]; T1 = t4[tb+1]; T2 = t4[tb+2]; T3 = t4[tb+3]; T4 = t4[tb+4];
        }

        // Partner exchange (symmetric): partner's last-two and first elements.
        // h=0 needs x38,x39,x20 ; h=1 needs x18,x19,x0 — both are partner's
        // X4.z, X4.w, X0.x under lane^1. Warp is convergent here.
        const float Lm2 = __shfl_xor_sync(0xFFFFFFFFu, X4.z, 1);
        const float Lm1 = __shfl_xor_sync(0xFFFFFFFFu, X4.w, 1);
        const float Rp0 = __shfl_xor_sync(0xFFFFFFFFu, X0.x, 1);

        const float a[20] = { X0.x,X0.y,X0.z,X0.w, X1.x,X1.y,X1.z,X1.w,
                              X2.x,X2.y,X2.z,X2.w, X3.x,X3.y,X3.z,X3.w,
                              X4.x,X4.y,X4.z,X4.w };
        const float yv[20] = { Y0.x,Y0.y,Y0.z,Y0.w, Y1.x,Y1.y,Y1.z,Y1.w,
                               Y2.x,Y2.y,Y2.z,Y2.w, Y3.x,Y3.y,Y3.z,Y3.w,
                               Y4.x,Y4.y,Y4.z,Y4.w };

        // ---- physics term: Lorenz-96 RHS fully in registers ----
        {
            float d;
            d = (a[0] - yv[0]) * 100.0f - ((a[1] - Lm2)  * Lm1   - a[0] + 8.0f);
            acc_pi += d * d;
            d = (a[1] - yv[1]) * 100.0f - ((a[2] - Lm1)  * a[0]  - a[1] + 8.0f);
            acc_pi += d * d;
            #pragma unroll
            for (int k = 2; k <= 18; ++k) {
                d = (a[k] - yv[k]) * 100.0f - ((a[k+1] - a[k-2]) * a[k-1] - a[k] + 8.0f);
                acc_pi += d * d;
            }
            d = (a[19] - yv[19]) * 100.0f - ((Rp0 - a[17]) * a[18] - a[19] + 8.0f);
            acc_pi += d * d;
        }

        // ---- data-driven term (h==0 lanes own cols 0..19 in registers) ----
        if (h == 0) {
            const float tt[20] = { T0.x,T0.y,T0.z,T0.w, T1.x,T1.y,T1.z,T1.w,
                                   T2.x,T2.y,T2.z,T2.w, T3.x,T3.y,T3.z,T3.w,
                                   T4.x,T4.y,T4.z,T4.w };
            #pragma unroll
            for (int k = 0; k < 20; ++k) {
                float e = a[k] - tt[k];
                acc_dd += e * e;
            }
        }
    }

    // ---- block reduction: warp shuffle (float) -> smem (double) ----
    #pragma unroll
    for (int o = 16; o; o >>= 1) {
        acc_dd += __shfl_xor_sync(0xFFFFFFFFu, acc_dd, o);
        acc_pi += __shfl_xor_sync(0xFFFFFFFFu, acc_pi, o);
    }
    __shared__ double wdd[WARPS], wpi[WARPS];
    __shared__ int s_last;
    const int lane5 = t & 31;
    if (lane5 == 0) { wdd[wid] = (double)acc_dd; wpi[wid] = (double)acc_pi; }
    __syncthreads();
    if (t == 0) {
        double a = 0.0, b = 0.0;
        #pragma unroll
        for (int k = 0; k < WARPS; ++k) { a += wdd[k]; b += wpi[k]; }
        g_part_dd[blockIdx.x] = a;
        g_part_pi[blockIdx.x] = b;
        __threadfence();
        unsigned int v = atomicAdd(&g_ticket, 1u);
        s_last = (v == (unsigned int)(gridDim.x - 1));
    }
    __syncthreads();

    // ---- last block performs the final reduction (fixed order: deterministic) ----
    if (s_last) {
        double a = 0.0, b = 0.0;
        for (int k = t; k < NBLOCKS; k += TPB) {
            a += g_part_dd[k];
            b += g_part_pi[k];
        }
        #pragma unroll
        for (int o = 16; o; o >>= 1) {
            a += __shfl_xor_sync(0xFFFFFFFFu, a, o);
            b += __shfl_xor_sync(0xFFFFFFFFu, b, o);
        }
        if (lane5 == 0) { wdd[wid] = a; wpi[wid] = b; }
        __syncthreads();
        if (t == 0) {
            double A = 0.0, B = 0.0;
            #pragma unroll
            for (int k = 0; k < WARPS; ++k) { A += wdd[k]; B += wpi[k]; }
            double l_dd = A / ((double)BATCHN * (double)NX);
            double l_pi = B / ((double)BATCHN * (double)NTOT);
            out[0] = (float)(l_dd + 0.1 * l_pi);   // total_loss
            out[1] = (float)l_dd;
            out[2] = (float)l_pi;
            g_ticket = 0;   // re-arm for next graph replay
        }
    }
}

extern "C" void kernel_launch(void* const* d_in, const int* in_sizes, int n_in,
                              void* d_out, int out_size)
{
    const float* pred = (const float*)d_in[0];   // predictions [524288, 40]
    const float* targ = (const float*)d_in[1];   // targets     [524288, 40]
    const float* ycur = (const float*)d_in[2];   // y_current   [524288, 40]
    float* out = (float*)d_out;                  // [total, l_dd, l_pi]

    hybrid_loss_kernel<<<NBLOCKS, TPB>>>(pred, targ, ycur, out);
}